// round 9
// baseline (speedup 1.0000x reference)
#include <cuda_runtime.h>
#include <math.h>

// QuanvolutionHybrid, reduced: only feats[:,0] (patch 0, wire0 <Z>) feeds the
// FC stage. Direct 4-qubit sim, 4 threads/sample. CNOT rings removed
// algebraically (GF(2) conjugation; masks validated in R8). FC circuit
// collapsed to q = alpha*cos(ez) + beta*sin(ez) with (alpha,beta) from the
// fixed 2x2 product V, computed per-thread as an independent stream that the
// scheduler interleaves into gate-phase stall slots (no extra barrier).
// __launch_bounds__(128,1) releases the 32-reg budget so gate-matrix LDS can
// be prefetched off the critical chain.

#define SHX(v, m) __shfl_xor_sync(0xffffffffu, (v), (m))
#define SH4(v, l) __shfl_sync(0xffffffffu, (v), (l), 4)

__device__ __forceinline__ void rot_mat_fast(float phi, float theta, float omega, float4* m) {
    // PennyLane Rot(phi,theta,omega) = RZ(omega) RY(theta) RZ(phi)
    float ct, st, ca, sa, cb, sb;
    __sincosf(0.5f * theta, &st, &ct);
    __sincosf(0.5f * (phi + omega), &sa, &ca);
    __sincosf(0.5f * (phi - omega), &sb, &cb);
    m[0] = make_float4( ct * ca, -ct * sa, -st * cb, -st * sb);  // m00, m01
    m[1] = make_float4( st * cb, -st * sb,  ct * ca,  ct * sa);  // m10, m11
}

// Conjugated two-level rotation (validated R8).
//   GM = lane-xor mask, TM = slot-xor mask, SG/ST = sigma lane/slot bits
#define GSLOT(T, GM, TM, SG, ST) {                                            \
    float apr = ar[(T) ^ (TM)], api = ai[(T) ^ (TM)];                         \
    if ((GM) != 0) { apr = SHX(apr, (GM)); api = SHX(api, (GM)); }            \
    const int side = pg ^ ((((ST) >> 1) & ((T) >> 1)) ^ ((ST) & (T) & 1));    \
    const float csr = side ? mB.z : mA.x, csi = side ? mB.w : mA.y;           \
    const float cpr = side ? mB.x : mA.z, cpi = side ? mB.y : mA.w;           \
    nr[T] = csr * ar[T] - csi * ai[T] + cpr * apr - cpi * api;                \
    ni[T] = csr * ai[T] + csi * ar[T] + cpr * api + cpi * apr; }

#define GGATE(GI, GM, TM, SG, ST) {                                           \
    const float4 mA = gm[GI][0], mB = gm[GI][1];                              \
    const int pg = (((SG) >> 1) & b1w) ^ ((SG) & b0w & 1);                    \
    float nr[4], ni[4];                                                       \
    GSLOT(0, GM, TM, SG, ST) GSLOT(1, GM, TM, SG, ST)                         \
    GSLOT(2, GM, TM, SG, ST) GSLOT(3, GM, TM, SG, ST)                         \
    ar[0] = nr[0]; ai[0] = ni[0]; ar[1] = nr[1]; ai[1] = ni[1];               \
    ar[2] = nr[2]; ai[2] = ni[2]; ar[3] = nr[3]; ai[3] = ni[3]; }

__global__ void __launch_bounds__(128, 1)
quanv_hybrid_kernel(const float* __restrict__ x,
                    const float* __restrict__ wq,    // [2,2,4,3]
                    const float* __restrict__ wfc,   // [3,3,1,3]
                    const float* __restrict__ Wout,  // [10,1]
                    const float* __restrict__ bout,  // [10]
                    float* __restrict__ out,         // [B,10]
                    int B)
{
    __shared__ float4 gm[25][2];   // [0..15] quanv gates, [16..24] fc gates
    __shared__ float  wob[20];     // wo[0..9], bo[0..9]

    const int tid = threadIdx.x;
    const int g   = tid & 3;
    const int s   = blockIdx.x * 32 + (tid >> 2);
    const int scl = (s < B) ? s : (B - 1);

    // Sample pixel load first (cold-miss latency overlaps prologue).
    const float pix = x[(size_t)scl * 784 + ((g & 1) + 28 * (g >> 1))];

    // ---- prologue: all 25 Rot matrices + head weights ----
    if (tid < 25) {
        const float* p = (tid < 16) ? (wq + tid * 3) : (wfc + (tid - 16) * 3);
        rot_mat_fast(p[0], p[1], p[2], gm[tid]);
    } else if (tid >= 32 && tid < 52) {
        const int l = tid - 32;
        wob[l] = __ldg((l < 10) ? (Wout + l) : (bout + (l - 10)));
    }

    float cg_, sg_;
    __sincosf(0.5f * pix, &sg_, &cg_);
    const float c0 = SH4(cg_, 0), s0 = SH4(sg_, 0);
    const float c1 = SH4(cg_, 1), s1 = SH4(sg_, 1);
    const float c2 = SH4(cg_, 2), s2 = SH4(sg_, 2);
    const float c3 = SH4(cg_, 3), s3 = SH4(sg_, 3);

    // Layout: lane bits (b1w,b0w) = (wire0,wire3); slot bits = (wire1,wire2)
    const int b1w = (g >> 1) & 1;
    const int b0w = g & 1;

    // RX product state: amp = (-i)^pops * prod(c or s per wire bit)
    float ar[4], ai[4];
    {
        const float fl = (b1w ? s0 : c0) * (b0w ? s3 : c3);
#define MKAMP(T) {                                                            \
        const int tb1 = (T) >> 1, tb0 = (T) & 1;                              \
        float mag = fl * (tb1 ? s1 : c1) * (tb0 ? s2 : c2);                   \
        int p_ = (b1w + b0w + tb1 + tb0) & 3;                                 \
        float sv = (p_ & 2) ? -mag : mag;                                     \
        ar[T] = (p_ & 1) ? 0.f : sv;                                          \
        ai[T] = (p_ & 1) ? -sv : 0.f; }
        MKAMP(0) MKAMP(1) MKAMP(2) MKAMP(3)
#undef MKAMP
    }

    __syncthreads();   // gate matrices + wob ready

    // ---- independent stream: V = fm[24]..fm[16] product (both columns) ----
    // (sample-independent; scheduler interleaves into gate-phase stall slots)
    float v0r = 1.f, v0i = 0.f, v1r = 0.f, v1i = 0.f;   // V|0> column
    float u0r = 0.f, u0i = 0.f, u1r = 1.f, u1i = 0.f;   // V|1> column
#pragma unroll
    for (int gi = 16; gi < 25; gi++) {
        const float4 mA = gm[gi][0];
        const float4 mB = gm[gi][1];
        float n0r = mA.x*v0r - mA.y*v0i + mA.z*v1r - mA.w*v1i;
        float n0i = mA.x*v0i + mA.y*v0r + mA.z*v1i + mA.w*v1r;
        float n1r = mB.x*v0r - mB.y*v0i + mB.z*v1r - mB.w*v1i;
        float n1i = mB.x*v0i + mB.y*v0r + mB.z*v1i + mB.w*v1r;
        v0r = n0r; v0i = n0i; v1r = n1r; v1i = n1i;
        float m0r = mA.x*u0r - mA.y*u0i + mA.z*u1r - mA.w*u1i;
        float m0i = mA.x*u0i + mA.y*u0r + mA.z*u1i + mA.w*u1r;
        float m1r = mB.x*u0r - mB.y*u0i + mB.z*u1r - mB.w*u1i;
        float m1i = mB.x*u0i + mB.y*u0r + mB.z*u1i + mB.w*u1r;
        u0r = m0r; u0i = m0i; u1r = m1r; u1i = m1i;
    }
    // alpha = |V00|^2 - |V10|^2 ; beta = Im(conj(V00)V01) - Im(conj(V10)V11)
    const float alpha = (v0r*v0r + v0i*v0i) - (v1r*v1r + v1i*v1i);
    const float beta  = (v0r*u0i - v0i*u0r) - (v1r*u1i - v1i*u1r);

    // ---- 16 conjugated rotations (rings eliminated; masks validated R8) ----
    GGATE( 0, 2, 0, 2, 0)
    GGATE( 1, 0, 2, 0, 2)
    GGATE( 2, 0, 1, 0, 1)
    GGATE( 3, 1, 0, 1, 0)
    GGATE( 4, 2, 2, 1, 3)
    GGATE( 5, 0, 3, 2, 2)
    GGATE( 6, 1, 1, 2, 3)
    GGATE( 7, 3, 2, 3, 3)
    GGATE( 8, 3, 3, 2, 3)
    GGATE( 9, 3, 1, 3, 3)
    GGATE(10, 2, 2, 3, 0)
    GGATE(11, 0, 3, 1, 1)
    GGATE(12, 0, 2, 1, 2)
    GGATE(13, 1, 3, 1, 0)
    GGATE(14, 2, 1, 2, 0)
    GGATE(15, 0, 1, 3, 1)

    // ---- <Z>: measurement mask folds back to wire0 = lane bit b1w ----
    float part = ar[0]*ar[0] + ai[0]*ai[0] + ar[1]*ar[1] + ai[1]*ai[1]
               + ar[2]*ar[2] + ai[2]*ai[2] + ar[3]*ar[3] + ai[3]*ai[3];
    part = b1w ? -part : part;
    part += SHX(part, 1);
    part += SHX(part, 2);
    const float ez = part;

    // ---- collapsed FC tail: q = alpha*cos(ez) + beta*sin(ez) ----
    float ce, se;
    __sincosf(ez, &se, &ce);
    const float q = alpha * ce + beta * se;

    // ---- Linear(1,10) + log_softmax; exps split across the 4 lanes ----
    float lg[10];
#pragma unroll
    for (int k = 0; k < 10; k++) lg[k] = fmaf(q, wob[k], wob[10 + k]);
    float pse = 0.f;
#pragma unroll
    for (int k = 0; k < 3; k++) {
        int idx = g + 4 * k;
        if (idx < 10) pse += __expf(lg[idx]);
    }
    pse += SHX(pse, 1);
    pse += SHX(pse, 2);
    const float off = __logf(pse);

    if (s < B) {
        float2* ob = (float2*)(out + (size_t)s * 10);   // 40B rows, 8B aligned
        ob[g] = make_float2(lg[2 * g] - off, lg[2 * g + 1] - off);
        if (g == 0) ob[4] = make_float2(lg[8] - off, lg[9] - off);
    }
}

extern "C" void kernel_launch(void* const* d_in, const int* in_sizes, int n_in,
                              void* d_out, int out_size) {
    const float* x    = (const float*)d_in[0];   // [B,784]
    const float* wq   = (const float*)d_in[1];   // [2,2,4,3]
    const float* wfc  = (const float*)d_in[2];   // [3,3,1,3]
    const float* Wout = (const float*)d_in[3];   // [10,1]
    const float* bout = (const float*)d_in[4];   // [10]
    float* out = (float*)d_out;                  // [B,10]

    int B = in_sizes[0] / 784;
    int blocks = (B + 31) / 32;                  // 32 samples per 128-thread block
    quanv_hybrid_kernel<<<blocks, 128>>>(x, wq, wfc, Wout, bout, out, B);
}

// round 10
// speedup vs baseline: 1.0048x; 1.0048x over previous
#include <cuda_runtime.h>
#include <math.h>

// QuanvolutionHybrid, reduced: only feats[:,0] (patch 0, wire0 <Z>) feeds the
// FC stage. Direct 4-qubit sim, 4 threads/sample. CNOT rings removed
// algebraically (GF(2) conjugation; masks validated R8). FC circuit collapsed
// to q = alpha*cos(ez) + beta*sin(ez) (validated R9). NEW in R10: fully
// warp-autonomous blocks — per-warp SMEM copies of gate matrices and head
// weights, __syncwarp() only, NO __syncthreads(): removes the block barrier
// and slowest-warp skew from the critical chain.

#define SHX(v, m) __shfl_xor_sync(0xffffffffu, (v), (m))
#define SH4(v, l) __shfl_sync(0xffffffffu, (v), (l), 4)

__device__ __forceinline__ void rot_mat_fast(float phi, float theta, float omega, float4* m) {
    // PennyLane Rot(phi,theta,omega) = RZ(omega) RY(theta) RZ(phi)
    float ct, st, ca, sa, cb, sb;
    __sincosf(0.5f * theta, &st, &ct);
    __sincosf(0.5f * (phi + omega), &sa, &ca);
    __sincosf(0.5f * (phi - omega), &sb, &cb);
    m[0] = make_float4( ct * ca, -ct * sa, -st * cb, -st * sb);  // m00, m01
    m[1] = make_float4( st * cb, -st * sb,  ct * ca,  ct * sa);  // m10, m11
}

// Conjugated two-level rotation (masks validated R8).
#define GSLOT(T, GM, TM, SG, ST) {                                            \
    float apr = ar[(T) ^ (TM)], api = ai[(T) ^ (TM)];                         \
    if ((GM) != 0) { apr = SHX(apr, (GM)); api = SHX(api, (GM)); }            \
    const int side = pg ^ ((((ST) >> 1) & ((T) >> 1)) ^ ((ST) & (T) & 1));    \
    const float csr = side ? mB.z : mA.x, csi = side ? mB.w : mA.y;           \
    const float cpr = side ? mB.x : mA.z, cpi = side ? mB.y : mA.w;           \
    nr[T] = csr * ar[T] - csi * ai[T] + cpr * apr - cpi * api;                \
    ni[T] = csr * ai[T] + csi * ar[T] + cpr * api + cpi * apr; }

#define GGATE(GI, GM, TM, SG, ST) {                                           \
    const float4 mA = gw[GI][0], mB = gw[GI][1];                              \
    const int pg = (((SG) >> 1) & b1w) ^ ((SG) & b0w & 1);                    \
    float nr[4], ni[4];                                                       \
    GSLOT(0, GM, TM, SG, ST) GSLOT(1, GM, TM, SG, ST)                         \
    GSLOT(2, GM, TM, SG, ST) GSLOT(3, GM, TM, SG, ST)                         \
    ar[0] = nr[0]; ai[0] = ni[0]; ar[1] = nr[1]; ai[1] = ni[1];               \
    ar[2] = nr[2]; ai[2] = ni[2]; ar[3] = nr[3]; ai[3] = ni[3]; }

__global__ void __launch_bounds__(128, 1)
quanv_hybrid_kernel(const float* __restrict__ x,
                    const float* __restrict__ wq,    // [2,2,4,3]
                    const float* __restrict__ wfc,   // [3,3,1,3]
                    const float* __restrict__ Wout,  // [10,1]
                    const float* __restrict__ bout,  // [10]
                    float* __restrict__ out,         // [B,10]
                    int B)
{
    // Per-warp private copies: no cross-warp synchronization anywhere.
    __shared__ float4 gmw[4][25][2];   // [0..15] quanv gates, [16..24] fc gates
    __shared__ float  wobw[4][20];     // wo[0..9], bo[0..9]

    const int tid  = threadIdx.x;
    const int wid  = tid >> 5;
    const int lane = tid & 31;
    const int g    = tid & 3;
    const int s    = blockIdx.x * 32 + (tid >> 2);
    const int scl  = (s < B) ? s : (B - 1);

    float4 (*gw)[2] = gmw[wid];
    float*  wob     = wobw[wid];

    // Sample pixel load first (cold-miss latency overlaps prologue).
    const float pix = x[(size_t)scl * 784 + ((g & 1) + 28 * (g >> 1))];

    // ---- per-warp prologue ----
    if (lane < 25) {
        const float* p = (lane < 16) ? (wq + lane * 3) : (wfc + (lane - 16) * 3);
        rot_mat_fast(p[0], p[1], p[2], gw[lane]);
    } else if (lane < 31) {
        // lanes 25..30: vector-load Wout/bout (cudaMalloc buffers: 16B aligned)
        const int q_   = lane - 25;        // 0..5
        const int half = (q_ >= 3);        // 0 = Wout, 1 = bout
        const int part = q_ - half * 3;    // 0,1,2
        const float* src = half ? bout : Wout;
        float* dst = wob + half * 10;
        if (part < 2) {
            float4 v = *(const float4*)(src + part * 4);
            dst[part * 4 + 0] = v.x; dst[part * 4 + 1] = v.y;
            dst[part * 4 + 2] = v.z; dst[part * 4 + 3] = v.w;
        } else {
            float2 v = *(const float2*)(src + 8);
            dst[8] = v.x; dst[9] = v.y;
        }
    }

    float cg_, sg_;
    __sincosf(0.5f * pix, &sg_, &cg_);
    const float c0 = SH4(cg_, 0), s0 = SH4(sg_, 0);
    const float c1 = SH4(cg_, 1), s1 = SH4(sg_, 1);
    const float c2 = SH4(cg_, 2), s2 = SH4(sg_, 2);
    const float c3 = SH4(cg_, 3), s3 = SH4(sg_, 3);

    // Layout: lane bits (b1w,b0w) = (wire0,wire3); slot bits = (wire1,wire2)
    const int b1w = (g >> 1) & 1;
    const int b0w = g & 1;

    // RX product state: amp = (-i)^pops * prod(c or s per wire bit)
    float ar[4], ai[4];
    {
        const float fl = (b1w ? s0 : c0) * (b0w ? s3 : c3);
#define MKAMP(T) {                                                            \
        const int tb1 = (T) >> 1, tb0 = (T) & 1;                              \
        float mag = fl * (tb1 ? s1 : c1) * (tb0 ? s2 : c2);                   \
        int p_ = (b1w + b0w + tb1 + tb0) & 3;                                 \
        float sv = (p_ & 2) ? -mag : mag;                                     \
        ar[T] = (p_ & 1) ? 0.f : sv;                                          \
        ai[T] = (p_ & 1) ? -sv : 0.f; }
        MKAMP(0) MKAMP(1) MKAMP(2) MKAMP(3)
#undef MKAMP
    }

    __syncwarp();   // own warp's gate matrices + weights visible

    // ---- independent stream: V = fm[24]..fm[16] product (both columns) ----
    float v0r = 1.f, v0i = 0.f, v1r = 0.f, v1i = 0.f;   // V|0> column
    float u0r = 0.f, u0i = 0.f, u1r = 1.f, u1i = 0.f;   // V|1> column
#pragma unroll
    for (int gi = 16; gi < 25; gi++) {
        const float4 mA = gw[gi][0];
        const float4 mB = gw[gi][1];
        float n0r = mA.x*v0r - mA.y*v0i + mA.z*v1r - mA.w*v1i;
        float n0i = mA.x*v0i + mA.y*v0r + mA.z*v1i + mA.w*v1r;
        float n1r = mB.x*v0r - mB.y*v0i + mB.z*v1r - mB.w*v1i;
        float n1i = mB.x*v0i + mB.y*v0r + mB.z*v1i + mB.w*v1r;
        v0r = n0r; v0i = n0i; v1r = n1r; v1i = n1i;
        float m0r = mA.x*u0r - mA.y*u0i + mA.z*u1r - mA.w*u1i;
        float m0i = mA.x*u0i + mA.y*u0r + mA.z*u1i + mA.w*u1r;
        float m1r = mB.x*u0r - mB.y*u0i + mB.z*u1r - mB.w*u1i;
        float m1i = mB.x*u0i + mB.y*u0r + mB.z*u1i + mB.w*u1r;
        u0r = m0r; u0i = m0i; u1r = m1r; u1i = m1i;
    }
    const float alpha = (v0r*v0r + v0i*v0i) - (v1r*v1r + v1i*v1i);
    const float beta  = (v0r*u0i - v0i*u0r) - (v1r*u1i - v1i*u1r);

    // ---- 16 conjugated rotations (rings eliminated; masks validated R8) ----
    GGATE( 0, 2, 0, 2, 0)
    GGATE( 1, 0, 2, 0, 2)
    GGATE( 2, 0, 1, 0, 1)
    GGATE( 3, 1, 0, 1, 0)
    GGATE( 4, 2, 2, 1, 3)
    GGATE( 5, 0, 3, 2, 2)
    GGATE( 6, 1, 1, 2, 3)
    GGATE( 7, 3, 2, 3, 3)
    GGATE( 8, 3, 3, 2, 3)
    GGATE( 9, 3, 1, 3, 3)
    GGATE(10, 2, 2, 3, 0)
    GGATE(11, 0, 3, 1, 1)
    GGATE(12, 0, 2, 1, 2)
    GGATE(13, 1, 3, 1, 0)
    GGATE(14, 2, 1, 2, 0)
    GGATE(15, 0, 1, 3, 1)

    // ---- <Z>: measurement mask folds back to wire0 = lane bit b1w ----
    float part = ar[0]*ar[0] + ai[0]*ai[0] + ar[1]*ar[1] + ai[1]*ai[1]
               + ar[2]*ar[2] + ai[2]*ai[2] + ar[3]*ar[3] + ai[3]*ai[3];
    part = b1w ? -part : part;
    part += SHX(part, 1);
    part += SHX(part, 2);
    const float ez = part;

    // ---- collapsed FC tail: q = alpha*cos(ez) + beta*sin(ez) ----
    float ce, se;
    __sincosf(ez, &se, &ce);
    const float q = alpha * ce + beta * se;

    // ---- Linear(1,10) + log_softmax; exps split across the 4 lanes ----
    float lg[10];
#pragma unroll
    for (int k = 0; k < 10; k++) lg[k] = fmaf(q, wob[k], wob[10 + k]);
    float pse = 0.f;
#pragma unroll
    for (int k = 0; k < 3; k++) {
        int idx = g + 4 * k;
        if (idx < 10) pse += __expf(lg[idx]);
    }
    pse += SHX(pse, 1);
    pse += SHX(pse, 2);
    const float off = __logf(pse);

    if (s < B) {
        float2* ob = (float2*)(out + (size_t)s * 10);   // 40B rows, 8B aligned
        ob[g] = make_float2(lg[2 * g] - off, lg[2 * g + 1] - off);
        if (g == 0) ob[4] = make_float2(lg[8] - off, lg[9] - off);
    }
}

extern "C" void kernel_launch(void* const* d_in, const int* in_sizes, int n_in,
                              void* d_out, int out_size) {
    const float* x    = (const float*)d_in[0];   // [B,784]
    const float* wq   = (const float*)d_in[1];   // [2,2,4,3]
    const float* wfc  = (const float*)d_in[2];   // [3,3,1,3]
    const float* Wout = (const float*)d_in[3];   // [10,1]
    const float* bout = (const float*)d_in[4];   // [10]
    float* out = (float*)d_out;                  // [B,10]

    int B = in_sizes[0] / 784;
    int blocks = (B + 31) / 32;                  // 32 samples per 128-thread block
    quanv_hybrid_kernel<<<blocks, 128>>>(x, wq, wfc, Wout, bout, out, B);
}